// round 1
// baseline (speedup 1.0000x reference)
#include <cuda_runtime.h>
#include <cuda_bf16.h>

// x:    [B=64, C=64, S=8192] float32
// mask: [B=64, S=8192] int32
// out:  patches [64, 512, 1024] float32  followed by  padding_mask [64, 512] float32
//
// patches[b, p, c*16 + j] = x[b, c, p*16 + j]   (stride == patch -> pure permutation)
// padding_mask[b, p] = (sum(mask[b, p*16 : p*16+16]) >= 8) ? 1.0f : 0.0f

#define B       64
#define C       64
#define S       8192
#define NP      512              // n_patches
#define CP      1024             // C * PATCH
#define PATCH_F4_PER_B   (NP * CP / 4)   // 131072 float4 per batch in output
#define F4_PER_P         (CP / 4)        // 256 float4 per patch row
#define TOTAL_OUT_F4     (B * PATCH_F4_PER_B)  // 8388608

__global__ void __launch_bounds__(256)
patch_permute_kernel(const float4* __restrict__ x4, float4* __restrict__ out4) {
    int i = blockIdx.x * 256 + threadIdx.x;          // one output float4 per thread
    // decompose output float4 index
    int b  = i >> 17;                                // / 131072
    int r  = i & (PATCH_F4_PER_B - 1);
    int p  = r >> 8;                                 // / 256
    int r2 = r & 255;
    int c  = r2 >> 2;                                // / 4
    int j4 = r2 & 3;
    // source float4 index into x: ((b*64 + c) * 8192 + p*16) / 4 + j4
    int src = ((b << 6) + c) * (S / 4) + (p << 2) + j4;
    out4[i] = x4[src];
}

__global__ void __launch_bounds__(256)
mask_kernel(const int4* __restrict__ m4, float* __restrict__ pm) {
    int t = blockIdx.x * 256 + threadIdx.x;          // one (b,p) per thread
    if (t >= B * NP) return;
    int b = t >> 9;                                  // / 512
    int p = t & (NP - 1);
    int base = (b * S + p * 16) >> 2;                // int4 index
    int s = 0;
    #pragma unroll
    for (int k = 0; k < 4; k++) {
        int4 v = m4[base + k];
        s += v.x + v.y + v.z + v.w;
    }
    pm[t] = (s >= 8) ? 1.0f : 0.0f;
}

extern "C" void kernel_launch(void* const* d_in, const int* in_sizes, int n_in,
                              void* d_out, int out_size) {
    const float4* x4 = (const float4*)d_in[0];
    const int4*   m4 = (const int4*)d_in[1];
    float* out = (float*)d_out;

    // patches: 8,388,608 float4 -> 32768 blocks x 256 threads
    patch_permute_kernel<<<TOTAL_OUT_F4 / 256, 256>>>(x4, (float4*)out);

    // padding mask written after patches region
    float* pm = out + (size_t)B * NP * CP;           // offset 33,554,432 floats
    mask_kernel<<<(B * NP + 255) / 256, 256>>>(m4, pm);
}

// round 2
// speedup vs baseline: 1.0223x; 1.0223x over previous
#include <cuda_runtime.h>
#include <cuda_bf16.h>

// x:    [B=64, C=64, S=8192] float32
// mask: [B=64, S=8192] int32
// out:  patches [64, 512, 1024] float32  followed by  padding_mask [64, 512] float32
//
// patches[b, p, c*16 + j] = x[b, c, p*16 + j]   (stride == patch -> pure permutation)
// padding_mask[b, p] = (sum(mask[b, p*16 : p*16+16]) >= 8) ? 1.0f : 0.0f
//
// Single fused launch: permute blocks + mask blocks in one grid so the tiny
// mask work overlaps the LTS-cap-bound permute instead of serializing after it.

#define B       64
#define C       64
#define S       8192
#define NP      512                       // n_patches
#define CP      1024                      // C * PATCH
#define PATCH_F4_PER_B   (NP * CP / 4)    // 131072 float4 per batch in output
#define TOTAL_OUT_F4     (B * PATCH_F4_PER_B)  // 8388608
#define PERMUTE_BLOCKS   (TOTAL_OUT_F4 / 256)  // 32768
#define MASK_THREADS     (B * NP)              // 32768
#define MASK_BLOCKS      ((MASK_THREADS + 255) / 256)  // 128

__global__ void __launch_bounds__(256)
fused_patch_kernel(const float4* __restrict__ x4,
                   const int4* __restrict__ m4,
                   float4* __restrict__ out4,
                   float* __restrict__ pm) {
    int blk = blockIdx.x;
    if (blk < PERMUTE_BLOCKS) {
        // ---- permute: one output float4 per thread, fully coalesced writes ----
        int i = blk * 256 + threadIdx.x;
        int b  = i >> 17;                         // / 131072
        int r  = i & (PATCH_F4_PER_B - 1);
        int p  = r >> 8;                          // / 256
        int r2 = r & 255;
        int c  = r2 >> 2;                         // / 4
        int j4 = r2 & 3;
        int src = ((b << 6) + c) * (S / 4) + (p << 2) + j4;
        out4[i] = x4[src];
    } else {
        // ---- mask: one (b,p) per thread ----
        int t = (blk - PERMUTE_BLOCKS) * 256 + threadIdx.x;
        if (t >= MASK_THREADS) return;
        int b = t >> 9;                           // / 512
        int p = t & (NP - 1);
        int base = (b * S + p * 16) >> 2;         // int4 index
        int s = 0;
        #pragma unroll
        for (int k = 0; k < 4; k++) {
            int4 v = m4[base + k];
            s += v.x + v.y + v.z + v.w;
        }
        pm[t] = (s >= 8) ? 1.0f : 0.0f;
    }
}

extern "C" void kernel_launch(void* const* d_in, const int* in_sizes, int n_in,
                              void* d_out, int out_size) {
    const float4* x4 = (const float4*)d_in[0];
    const int4*   m4 = (const int4*)d_in[1];
    float* out = (float*)d_out;
    float* pm  = out + (size_t)B * NP * CP;       // padding_mask after patches

    fused_patch_kernel<<<PERMUTE_BLOCKS + MASK_BLOCKS, 256>>>(
        x4, m4, (float4*)out, pm);
}

// round 3
// speedup vs baseline: 1.1442x; 1.1192x over previous
#include <cuda_runtime.h>
#include <cuda_bf16.h>

// x:    [B=64, C=64, S=8192] float32
// mask: [B=64, S=8192] int32
// out:  patches [64, 512, 1024] float32  followed by  padding_mask [64, 512] float32
//
// patches[b, p, c*16 + j] = x[b, c, p*16 + j]   (stride == patch -> pure permutation)
// padding_mask[b, p] = (sum(mask[b, p*16 : p*16+16]) >= 8) ? 1.0f : 0.0f
//
// Fused single launch. Permute blocks use ILP=4: four independent LDG.128
// in flight per thread before the stores, to cover DRAM latency (R2 ncu:
// DRAM only 66%, occ 73%, issue 11% -> latency-exposure bound at MLP=1).

#define B       64
#define C       64
#define S       8192
#define NP      512                       // n_patches
#define CP      1024                      // C * PATCH
#define TOTAL_OUT_F4     (B * NP * CP / 4)       // 8388608
#define F4_PER_BLOCK     1024                    // 256 threads x 4
#define PERMUTE_BLOCKS   (TOTAL_OUT_F4 / F4_PER_BLOCK)  // 8192
#define MASK_THREADS     (B * NP)                // 32768
#define MASK_BLOCKS      ((MASK_THREADS + 255) / 256)   // 128

__device__ __forceinline__ int src_of(int i) {
    // output float4 index -> source float4 index in x
    int b  = i >> 17;                     // / 131072 (f4 per batch)
    int r  = i & ((NP * CP / 4) - 1);
    int p  = r >> 8;                      // / 256
    int r2 = r & 255;
    int c  = r2 >> 2;
    int j4 = r2 & 3;
    return ((b << 6) + c) * (S / 4) + (p << 2) + j4;
}

__global__ void __launch_bounds__(256)
fused_patch_kernel(const float4* __restrict__ x4,
                   const int4* __restrict__ m4,
                   float4* __restrict__ out4,
                   float* __restrict__ pm) {
    int blk = blockIdx.x;
    if (blk < PERMUTE_BLOCKS) {
        int base = blk * F4_PER_BLOCK + threadIdx.x;
        float4 v[4];
        #pragma unroll
        for (int k = 0; k < 4; k++)
            v[k] = x4[src_of(base + k * 256)];
        #pragma unroll
        for (int k = 0; k < 4; k++)
            out4[base + k * 256] = v[k];
    } else {
        int t = (blk - PERMUTE_BLOCKS) * 256 + threadIdx.x;
        if (t >= MASK_THREADS) return;
        int b = t >> 9;                   // / 512
        int p = t & (NP - 1);
        int mbase = (b * S + p * 16) >> 2;
        int s = 0;
        #pragma unroll
        for (int k = 0; k < 4; k++) {
            int4 m = m4[mbase + k];
            s += m.x + m.y + m.z + m.w;
        }
        pm[t] = (s >= 8) ? 1.0f : 0.0f;
    }
}

extern "C" void kernel_launch(void* const* d_in, const int* in_sizes, int n_in,
                              void* d_out, int out_size) {
    const float4* x4 = (const float4*)d_in[0];
    const int4*   m4 = (const int4*)d_in[1];
    float* out = (float*)d_out;
    float* pm  = out + (size_t)B * NP * CP;

    fused_patch_kernel<<<PERMUTE_BLOCKS + MASK_BLOCKS, 256>>>(
        x4, m4, (float4*)out, pm);
}